// round 5
// baseline (speedup 1.0000x reference)
#include <cuda_runtime.h>
#include <cstdint>
#include <math.h>
#include <math_constants.h>

#define NCTA     128
#define NTHREADS 128
#define HDIM     512
#define TSTEPS   31
#define BSEQ     512
#define OUTC     12

// ---------------- device globals (scratch) ----------------
__device__ float    g_ys0[BSEQ * HDIM];
__device__ float    g_ys1[BSEQ * HDIM];
__device__ float    g_scale[HDIM];
__device__ float    g_shift[HDIM];
__device__ unsigned g_count0;   // returns to 0 after every barrier
__device__ unsigned g_gen0;     // equality-spin => safe across graph replays

__device__ __forceinline__ void barrier_gpu(unsigned id) {
    __threadfence();
    unsigned old = atomicAdd(&g_count0, 1u);
    if (old == NCTA - 1u) {
        atomicExch(&g_count0, 0u);
        __threadfence();
        asm volatile("st.release.gpu.u32 [%0], %1;" :: "l"(&g_gen0), "r"(id) : "memory");
    } else {
        unsigned v;
        do {
            asm volatile("ld.acquire.gpu.u32 %0, [%1];" : "=r"(v) : "l"(&g_gen0) : "memory");
        } while (v != id);
    }
}

__device__ __forceinline__ float sigm(float x) { return 1.0f / (1.0f + expf(-x)); }

// JAX threefry2x32 (20 rounds)
__device__ __forceinline__ uint2 tf2x32(unsigned k0, unsigned k1, unsigned x0, unsigned x1) {
    unsigned ks2 = k0 ^ k1 ^ 0x1BD11BDAu;
    x0 += k0; x1 += k1;
#define TFR(r) { x0 += x1; x1 = __funnelshift_l(x1, x1, r); x1 ^= x0; }
    TFR(13) TFR(15) TFR(26) TFR(6);  x0 += k1;  x1 += ks2 + 1u;
    TFR(17) TFR(29) TFR(16) TFR(24); x0 += ks2; x1 += k0 + 2u;
    TFR(13) TFR(15) TFR(26) TFR(6);  x0 += k0;  x1 += k1 + 3u;
    TFR(17) TFR(29) TFR(16) TFR(24); x0 += k1;  x1 += ks2 + 4u;
    TFR(13) TFR(15) TFR(26) TFR(6);  x0 += ks2; x1 += k0 + 5u;
#undef TFR
    return make_uint2(x0, x1);
}

// Partitionable threefry (modern JAX default, jax_threefry_partitionable=True):
// 32-bit random_bits element m: counter = (hi=0, lo=m), output = out.x ^ out.y
__device__ __forceinline__ unsigned rbits_p(unsigned k0, unsigned k1, unsigned m) {
    uint2 p = tf2x32(k0, k1, 0u, m);
    return p.x ^ p.y;
}

// ---------------- smem layout (float offsets) ----------------
#define OFF_W0   0
#define OFF_W1I  8192
#define OFF_W1H  16384
#define OFF_H0S  24576
#define OFF_H1S  25088
#define OFF_GROW 25600
#define OFF_A0S  27648
#define OFF_B1S  27664
#define OFF_G0S  27680
#define OFF_G1S  27696
#define OFF_C0S  27712
#define OFF_C1S  27716
#define OFF_SUM  27720
#define OFF_SSQ  27724
#define SMEM_FLOATS 27728
#define SMEM_BYTES  (SMEM_FLOATS * 4)

__global__ void __launch_bounds__(NTHREADS, 1)
net_kernel(const float* __restrict__ Wih0, const float* __restrict__ Whh0,
           const float* __restrict__ b0,   const float* __restrict__ Wih1,
           const float* __restrict__ Whh1, const float* __restrict__ b1,
           const float* __restrict__ gamma,const float* __restrict__ beta,
           const float* __restrict__ Wout, const float* __restrict__ bout,
           const float* __restrict__ h0in, const float* __restrict__ c0in,
           float* __restrict__ out)
{
    extern __shared__ float smem[];
    float* w0s  = smem + OFF_W0;
    float* w1i  = smem + OFF_W1I;
    float* w1h  = smem + OFF_W1H;
    float* h0s  = smem + OFF_H0S;
    float* h1s  = smem + OFF_H1S;
    float* grow = smem + OFF_GROW;
    float* a0s  = smem + OFF_A0S;
    float* b1s  = smem + OFF_B1S;
    float* g0s  = smem + OFF_G0S;
    float* g1s  = smem + OFF_G1S;
    float* c0s  = smem + OFF_C0S;
    float* c1s  = smem + OFF_C1S;
    float* sums = smem + OFF_SUM;
    float* ssqs = smem + OFF_SSQ;

    const int tid  = threadIdx.x;
    const int blk  = blockIdx.x;
    const int w    = tid >> 5;
    const int lane = tid & 31;

    // ---- load this CTA's weight slices (local row lr: gate=lr>>2, e=lr&3) ----
    for (int idx = tid; idx < 16 * 128; idx += NTHREADS) {
        int lr = idx >> 7, c4 = idx & 127;
        int gr = ((lr >> 2) << 9) + (blk << 2) + (lr & 3);
        ((float4*)w0s)[idx] = ((const float4*)Whh0)[gr * 128 + c4];
        ((float4*)w1i)[idx] = ((const float4*)Wih1)[gr * 128 + c4];
        ((float4*)w1h)[idx] = ((const float4*)Whh1)[gr * 128 + c4];
    }
    if (tid < 16) {
        int lr = tid;
        int gr = ((lr >> 2) << 9) + (blk << 2) + (lr & 3);
        float s = 0.0f;
        for (int k = 0; k < 64; k++) s += Wih0[gr * 64 + k];   // x is all-ones
        a0s[lr] = s + b0[gr];
        b1s[lr] = b1[gr];
    }
    if (tid < 4) {
        c0s[tid] = c0in[blk * 4 + tid];
        c1s[tid] = c0in[512 + blk * 4 + tid];
    }
    for (int i = tid; i < HDIM; i += NTHREADS) {
        h0s[i] = h0in[i];
        h1s[i] = h0in[512 + i];
    }
    __syncthreads();

    unsigned bar = 0;

    for (int iter = 0; iter < TSTEPS; ++iter) {
        if (tid < 4) { sums[tid] = 0.0f; ssqs[tid] = 0.0f; }
        __syncthreads();

        // ---- recurrence: layer1 pipelined one step behind layer0 ----
        for (int t = 0; t <= BSEQ; ++t) {
            const bool doL0 = (t < BSEQ);
            const bool doL1 = (t > 0);

            float4 hv0[4], hv1[4];
#pragma unroll
            for (int c = 0; c < 4; c++) hv0[c] = ((float4*)h0s)[c * 32 + lane];
#pragma unroll
            for (int c = 0; c < 4; c++) hv1[c] = ((float4*)h1s)[c * 32 + lane];

            float acc0[4] = {0, 0, 0, 0}, acc1[4] = {0, 0, 0, 0};
            if (doL0) {
#pragma unroll
                for (int c = 0; c < 4; c++) {
                    float4 h = hv0[c];
#pragma unroll
                    for (int r = 0; r < 4; r++) {
                        float4 wv = ((float4*)w0s)[(w * 4 + r) * 128 + c * 32 + lane];
                        acc0[r] += wv.x * h.x + wv.y * h.y + wv.z * h.z + wv.w * h.w;
                    }
                }
            }
            if (doL1) {
#pragma unroll
                for (int c = 0; c < 4; c++) {
                    float4 ha = hv0[c], hb = hv1[c];
#pragma unroll
                    for (int r = 0; r < 4; r++) {
                        float4 wv = ((float4*)w1i)[(w * 4 + r) * 128 + c * 32 + lane];
                        float4 uv = ((float4*)w1h)[(w * 4 + r) * 128 + c * 32 + lane];
                        acc1[r] += wv.x * ha.x + wv.y * ha.y + wv.z * ha.z + wv.w * ha.w
                                 + uv.x * hb.x + uv.y * hb.y + uv.z * hb.z + uv.w * hb.w;
                    }
                }
            }
#pragma unroll
            for (int r = 0; r < 4; r++) {
#pragma unroll
                for (int off = 16; off > 0; off >>= 1) {
                    acc0[r] += __shfl_xor_sync(0xffffffffu, acc0[r], off);
                    acc1[r] += __shfl_xor_sync(0xffffffffu, acc1[r], off);
                }
            }
            if (lane == 0) {
#pragma unroll
                for (int r = 0; r < 4; r++) {
                    g0s[w * 4 + r] = acc0[r] + a0s[w * 4 + r];
                    g1s[w * 4 + r] = acc1[r] + b1s[w * 4 + r];
                }
            }
            __syncthreads();

            bar++;
            if (tid < 32) {  // warp 0: cell updates + publish + global barrier
                if (lane < 4 && doL0) {
                    int e = lane;
                    float gi = g0s[e], gf = g0s[4 + e], gg = g0s[8 + e], go = g0s[12 + e];
                    float c = sigm(gf) * c0s[e] + sigm(gi) * tanhf(gg);
                    c0s[e] = c;
                    float hv = sigm(go) * tanhf(c);
                    __stcg(&g_ys0[t * HDIM + blk * 4 + e], hv);
                }
                if (lane >= 4 && lane < 8 && doL1) {
                    int e = lane - 4;
                    float gi = g1s[e], gf = g1s[4 + e], gg = g1s[8 + e], go = g1s[12 + e];
                    float c = sigm(gf) * c1s[e] + sigm(gi) * tanhf(gg);
                    c1s[e] = c;
                    float hv = sigm(go) * tanhf(c);
                    sums[e] += hv;
                    ssqs[e] += hv * hv;
                    __stcg(&g_ys1[(t - 1) * HDIM + blk * 4 + e], hv);
                }
                __syncwarp();
                if (lane == 0) barrier_gpu(bar);
            }
            __syncthreads();

            if (doL0) ((float4*)h0s)[tid] = __ldcg(((const float4*)(g_ys0 + t * HDIM)) + tid);
            if (doL1) ((float4*)h1s)[tid] = __ldcg(((const float4*)(g_ys1 + (t - 1) * HDIM)) + tid);
            __syncthreads();
        }

        // ---- batchnorm stats (biased var over the 512 steps) ----
        bar++;
        if (tid < 32) {
            if (lane < 4) {
                int j = blk * 4 + lane;
                float mu  = sums[lane] * (1.0f / 512.0f);
                float var = ssqs[lane] * (1.0f / 512.0f) - mu * mu;
                float inv = 1.0f / sqrtf(var + 1e-5f);
                float sc  = gamma[j] * inv;
                __stcg(&g_scale[j], sc);
                __stcg(&g_shift[j], beta[j] - mu * sc);
            }
            __syncwarp();
            if (lane == 0) barrier_gpu(bar);
        }
        __syncthreads();

        // ---- BN + gaussian + logits + threefry categorical sampling ----
        {
            int b = blk * 4 + w;            // this warp's sequence row
            float* gr = grow + w * 512;
#pragma unroll
            for (int c = 0; c < 16; c++) {
                int col = c * 32 + lane;
                float v  = __ldcg(&g_ys1[b * HDIM + col]);
                float yn = v * __ldcg(&g_scale[col]) + __ldcg(&g_shift[col]);
                gr[col] = expf(-yn * yn);
            }
            __syncwarp();

            float logit = -CUDART_INF_F;
            if (lane < OUTC) {
                float acc = bout[lane];
                const float* wrow = Wout + lane * HDIM;
#pragma unroll 8
                for (int k = 0; k < HDIM; k++) acc += gr[k] * __ldg(wrow + k);
                logit = acc;
            }

            // Partitionable split: keys[i] = threefry2x32(key(42), (0, i)) — full pair
            uint2 kp = tf2x32(0u, 42u, 0u, (unsigned)iter);
            unsigned k0 = kp.x, k1 = kp.y;
            bool full = (iter < 15);

            float v = -CUDART_INF_F;
            int idx = lane;
            bool cand = full ? (lane < 12) : (lane >= 8 && lane < 12);
            if (cand) {
                unsigned m = full ? (unsigned)(b * 12 + lane) : (unsigned)(b * 4 + (lane - 8));
                unsigned bits = rbits_p(k0, k1, m);   // counter (0, m), xor-folded
                float u = __uint_as_float((bits >> 9) | 0x3f800000u) - 1.0f;
                u = fmaxf(u, 1.17549435e-38f);
                float gum = -logf(-logf(u));
                v = gum + logit;
            }
#pragma unroll
            for (int off = 16; off > 0; off >>= 1) {
                float ov = __shfl_xor_sync(0xffffffffu, v, off);
                int   oi = __shfl_xor_sync(0xffffffffu, idx, off);
                if (ov > v || (ov == v && oi < idx)) { v = ov; idx = oi; }
            }
            // log_softmax over FULL 12 logits, gathered at the action
            float lm = logit;
#pragma unroll
            for (int off = 16; off > 0; off >>= 1) lm = fmaxf(lm, __shfl_xor_sync(0xffffffffu, lm, off));
            float e = (lane < OUTC) ? expf(logit - lm) : 0.0f;
#pragma unroll
            for (int off = 16; off > 0; off >>= 1) e += __shfl_xor_sync(0xffffffffu, e, off);
            float la = __shfl_sync(0xffffffffu, logit, idx);
            float lp = la - lm - logf(e);

            if (lane == 0) {
                out[iter * BSEQ + b]                 = (float)idx;
                out[TSTEPS * BSEQ + iter * BSEQ + b] = lp;
            }
        }

        // ---- protect ys buffers before next iteration overwrites ----
        __syncthreads();
        bar++;
        if (tid == 0) barrier_gpu(bar);
        __syncthreads();
    }
}

extern "C" void kernel_launch(void* const* d_in, const int* in_sizes, int n_in,
                              void* d_out, int out_size) {
    (void)in_sizes; (void)n_in; (void)out_size;
    const float* Wih0  = (const float*)d_in[0];
    const float* Whh0  = (const float*)d_in[1];
    const float* b0    = (const float*)d_in[2];
    const float* Wih1  = (const float*)d_in[3];
    const float* Whh1  = (const float*)d_in[4];
    const float* b1    = (const float*)d_in[5];
    const float* gamma = (const float*)d_in[6];
    const float* beta  = (const float*)d_in[7];
    const float* Wout  = (const float*)d_in[8];
    const float* bout  = (const float*)d_in[9];
    const float* h0in  = (const float*)d_in[10];
    const float* c0in  = (const float*)d_in[11];
    float* out = (float*)d_out;

    cudaFuncSetAttribute(net_kernel, cudaFuncAttributeMaxDynamicSharedMemorySize, SMEM_BYTES);
    net_kernel<<<NCTA, NTHREADS, SMEM_BYTES>>>(Wih0, Whh0, b0, Wih1, Whh1, b1,
                                               gamma, beta, Wout, bout, h0in, c0in, out);
}